// round 17
// baseline (speedup 1.0000x reference)
#include <cuda_runtime.h>
#include <cuda_fp16.h>

#define B_ROWS   16384
#define K_FEATS  32
#define FULLMASK 0xFFFFFFFFu

#define NBLOCKS   592            // 4 per SM on 148 SMs
#define NPAIRS    (NBLOCKS * 4)  // 2368 pair-slots
#define TBL_BLOCKS 5120

// fp16 copy of ft_w: 40960 x 256 halves = 20MB (128 half2 per row)
__device__ __half2 g_ftw_h[40960 * 128];
// fc1_w transposed: [iq][j] float4
__device__ float4 g_fc1T[128 * 32];
// dynamic row counter (reset by prep_all every replay)
__device__ int g_ctr;

// ---- merged prep: fp16 table + fc1 transpose + counter reset ----
__global__ __launch_bounds__(256) void prep_all(const float* __restrict__ ft_w,
                                                const float* __restrict__ fc1_w) {
    const int b = blockIdx.x;
    if (b == 0 && threadIdx.x == 0)
        g_ctr = NPAIRS;              // rows 0..NPAIRS-1 statically pre-assigned
    if (b < TBL_BLOCKS) {
        int i = b * blockDim.x + threadIdx.x;
        const float4 v0 = __ldg((const float4*)ft_w + i * 2);
        const float4 v1 = __ldg((const float4*)ft_w + i * 2 + 1);
        uint4 r;
        __half2 h0 = __floats2half2_rn(v0.x, v0.y);
        __half2 h1 = __floats2half2_rn(v0.z, v0.w);
        __half2 h2 = __floats2half2_rn(v1.x, v1.y);
        __half2 h3 = __floats2half2_rn(v1.z, v1.w);
        r.x = *(unsigned*)&h0; r.y = *(unsigned*)&h1;
        r.z = *(unsigned*)&h2; r.w = *(unsigned*)&h3;
        ((uint4*)g_ftw_h)[i] = r;
    } else {
        int t = (b - TBL_BLOCKS) * blockDim.x + threadIdx.x;
        if (t < 128 * 32) {
            int iq = t >> 5;
            int j  = t & 31;
            const float* p = fc1_w + j * 512 + iq * 4;
            g_fc1T[t] = make_float4(p[0], p[1], p[2], p[3]);
        }
    }
    cudaTriggerProgrammaticLaunchCompletion();
}

__device__ __forceinline__ float4 clip01(float4 v) {
    v.x = fminf(fmaxf(v.x, 0.0f), 1.0f);
    v.y = fminf(fmaxf(v.y, 0.0f), 1.0f);
    v.z = fminf(fmaxf(v.z, 0.0f), 1.0f);
    v.w = fminf(fmaxf(v.w, 0.0f), 1.0f);
    return v;
}

__device__ __forceinline__ void acc8(float4& a0, float4& a1, float m, uint4 r) {
    const __half2* h = (const __half2*)&r;
    float2 f0 = __half22float2(h[0]);
    float2 f1 = __half22float2(h[1]);
    float2 f2 = __half22float2(h[2]);
    float2 f3 = __half22float2(h[3]);
    a0.x = fmaf(m, f0.x, a0.x);  a0.y = fmaf(m, f0.y, a0.y);
    a0.z = fmaf(m, f1.x, a0.z);  a0.w = fmaf(m, f1.y, a0.w);
    a1.x = fmaf(m, f2.x, a1.x);  a1.y = fmaf(m, f2.y, a1.y);
    a1.z = fmaf(m, f3.x, a1.z);  a1.w = fmaf(m, f3.y, a1.w);
}

__global__ __launch_bounds__(256, 4)
void nnue_kernel(const int*   __restrict__ wft_ics,
                 const float* __restrict__ wft_vals,
                 const int*   __restrict__ bft_ics,
                 const float* __restrict__ bft_vals,
                 const int*   __restrict__ stm,
                 const float* __restrict__ ft_b,
                 const float* __restrict__ fc1_b,
                 const float* __restrict__ fc2_w,
                 const float* __restrict__ fc2_b,
                 const float* __restrict__ fco_w,
                 const float* __restrict__ fco_b,
                 float*       __restrict__ out)
{
    __shared__ float fc2T[32 * 33];        // padded: conflict-free write + read
    __shared__ int2  s_list[4][2][K_FEATS];// [pair][role][k] compacted (off,val)
    __shared__ float s_x[4][520];          // per-pair x[512] + pad
    __shared__ float s_h1p[4][2][32];      // FC1 partials
    __shared__ int2  s_row[4][2];          // (row, stm), double-buffered

    const int tid  = threadIdx.x;
    const int lane = tid & 31;
    const int warp = tid >> 5;     // 0..7
    const int role = warp & 1;     // 0 = w-transformer, 1 = b-transformer
    const int pair = warp >> 1;    // 0..3
    const int barid = pair + 1;    // named barriers 1..4

    // ---- block staging ----
    for (int idx = tid; idx < 1024; idx += 256)
        fc2T[(idx & 31) * 33 + (idx >> 5)] = fc2_w[idx];   // stride-33: no conflicts

    const float4 bias0 = *(const float4*)(ft_b + lane * 8);
    const float4 bias1 = *(const float4*)(ft_b + lane * 8 + 4);
    const float b1j = __ldg(fc1_b + lane);
    const float b2j = __ldg(fc2_b + lane);
    const float fcw = __ldg(fco_w + lane);
    const float fcb = __ldg(fco_b);

    const int*   ics  = role ? bft_ics  : wft_ics;
    const float* vals = role ? bft_vals : wft_vals;

    // static first row per pair
    const int pid = blockIdx.x * 4 + pair;
    if (role == 0 && lane == 0)
        s_row[pair][0] = make_int2(pid, __ldg(stm + pid));
    __syncthreads();

    // PDL: table + fc1T + counter ready
    cudaGridDependencySynchronize();

    int par = 0;
    while (true) {
        const int2 rs = s_row[pair][par];
        const int row = rs.x;
        if (row >= B_ROWS) break;

        // prefetch next row assignment (hidden under this row's gather)
        if (role == 0 && lane == 0) {
            const int nr = atomicAdd(&g_ctr, 1);
            const int s2 = (nr < B_ROWS) ? __ldg(stm + nr) : 0;
            s_row[pair][par ^ 1] = make_int2(nr, s2);
        }

        // load + compact this warp's 32 (idx,val) in original order
        const int gi = row * K_FEATS + lane;
        const int   fi = __ldg(ics + gi);
        const float fv = __ldg(vals + gi);
        const bool act = (fi >= 0);
        const unsigned m = __ballot_sync(FULLMASK, act);
        const int pos = __popc(m & ((1u << lane) - 1));
        const int cnt = __popc(m);
        if (act) s_list[pair][role][pos] = make_int2(fi * 128, __float_as_int(fv));
        __syncwarp();

        // gather this transformer's 256 columns (8 floats/lane)
        float4 a0 = bias0, a1 = bias1;
        const int2* lst = s_list[pair][role];
        #pragma unroll 4
        for (int k = 0; k < cnt; k++) {
            const int2 f = lst[k];
            const uint4 rv = __ldcg((const uint4*)(g_ftw_h + f.x) + lane);
            acc8(a0, a1, __int_as_float(f.y), rv);
        }

        // clip + store to the stm-selected half: (role ^ stm) ? hi : lo
        float4* xr = (float4*)(s_x[pair] + ((role ^ rs.y) ? 256 : 0));
        xr[lane * 2]     = clip01(a0);
        xr[lane * 2 + 1] = clip01(a1);

        asm volatile("bar.sync %0, 64;" :: "r"(barid) : "memory");   // both halves of x ready

        // FC1 partial over this warp's input half (iq 64 per warp)
        {
            float p = 0.0f;
            const float4* x4 = (const float4*)s_x[pair];
            const int iq0 = role * 64;
            #pragma unroll 4
            for (int q = 0; q < 64; q++) {
                const int iq = iq0 + q;
                const float4 w  = g_fc1T[iq * 32 + lane];   // 128B line, L1-hot
                const float4 xv = x4[iq];                   // broadcast LDS
                p = fmaf(w.x, xv.x, fmaf(w.y, xv.y, fmaf(w.z, xv.z, fmaf(w.w, xv.w, p))));
            }
            s_h1p[pair][role][lane] = p;
        }

        asm volatile("bar.sync %0, 64;" :: "r"(barid) : "memory");   // partials ready

        if (role == 0) {
            float h1 = s_h1p[pair][0][lane] + s_h1p[pair][1][lane] + b1j;
            h1 = fminf(fmaxf(h1, 0.0f), 1.0f);
            float h2 = b2j;
            #pragma unroll
            for (int i = 0; i < 32; i++)
                h2 = fmaf(fc2T[i * 33 + lane], __shfl_sync(FULLMASK, h1, i), h2);
            h2 = fminf(fmaxf(h2, 0.0f), 1.0f);

            float o = h2 * fcw;
            #pragma unroll
            for (int off = 16; off; off >>= 1)
                o += __shfl_xor_sync(FULLMASK, o, off);
            if (lane == 0)
                out[row] = o + fcb;
        }

        par ^= 1;
    }
}

extern "C" void kernel_launch(void* const* d_in, const int* in_sizes, int n_in,
                              void* d_out, int out_size)
{
    const int*   wft_ics  = (const int*)  d_in[0];
    const float* wft_vals = (const float*)d_in[1];
    const int*   bft_ics  = (const int*)  d_in[2];
    const float* bft_vals = (const float*)d_in[3];
    const int*   stm      = (const int*)  d_in[4];
    const float* ft_w     = (const float*)d_in[5];
    const float* ft_b     = (const float*)d_in[6];
    const float* fc1_w    = (const float*)d_in[7];
    const float* fc1_b    = (const float*)d_in[8];
    const float* fc2_w    = (const float*)d_in[9];
    const float* fc2_b    = (const float*)d_in[10];
    const float* fco_w    = (const float*)d_in[11];
    const float* fco_b    = (const float*)d_in[12];
    float* out = (float*)d_out;

    prep_all<<<TBL_BLOCKS + 16, 256>>>(ft_w, fc1_w);

    cudaLaunchConfig_t cfg = {};
    cfg.gridDim  = dim3(NBLOCKS);
    cfg.blockDim = dim3(256);
    cfg.dynamicSmemBytes = 0;
    cfg.stream = 0;
    cudaLaunchAttribute attrs[1];
    attrs[0].id = cudaLaunchAttributeProgrammaticStreamSerialization;
    attrs[0].val.programmaticStreamSerializationAllowed = 1;
    cfg.attrs = attrs;
    cfg.numAttrs = 1;
    cudaLaunchKernelEx(&cfg, nnue_kernel,
                       wft_ics, wft_vals, bft_ics, bft_vals, stm,
                       ft_b, fc1_b, fc2_w, fc2_b, fco_w, fco_b, out);
}